// round 1
// baseline (speedup 1.0000x reference)
#include <cuda_runtime.h>

// ---------------------------------------------------------------------------
// Decoder: 2-layer LSTM (H=256) over T=20 steps, BS=8192, then mu/logvar/sample
// projections (F=80). Persistent-CTA design: each CTA owns 32 batch rows and
// runs the full time loop with h/c state in SMEM. All GEMV math uses packed
// fma.rn.f32x2 (FFMA2) — 2 batch rows per instruction.
// ---------------------------------------------------------------------------

#define ULL unsigned long long
#define T_STEPS 20
#define HPAD 34   // padded row stride for [unit][row] h-buffers (bank spread)

__device__ __forceinline__ ULL pack2(float x, float y) {
    ULL r; asm("mov.b64 %0, {%1, %2};" : "=l"(r) : "f"(x), "f"(y)); return r;
}
__device__ __forceinline__ float2 unpack2(ULL v) {
    float2 r; asm("mov.b64 {%0, %1}, %2;" : "=f"(r.x), "=f"(r.y) : "l"(v)); return r;
}
__device__ __forceinline__ ULL fma2(ULL a, ULL b, ULL c) {
    ULL d; asm("fma.rn.f32x2 %0, %1, %2, %3;" : "=l"(d) : "l"(a), "l"(b), "l"(c)); return d;
}
__device__ __forceinline__ float sigf(float x)  { return __fdividef(1.f, 1.f + __expf(-x)); }
__device__ __forceinline__ float tanhe(float x) { return __fdividef(2.f, 1.f + __expf(-2.f * x)) - 1.f; }

// Time-invariant layer-1 input projection: xw1 = concat(z1,z2) @ W1 + b1
__device__ float g_xw1[8192u * 1024u];   // 32 MB static scratch (allowed)

// grid 1024, block 256: each block computes 8 rows x 1024 cols of xw1
__global__ void xw1_kernel(const float* __restrict__ z1, const float* __restrict__ z2,
                           const float* __restrict__ W1, const float* __restrict__ b1) {
    __shared__ float zt[8][64];
    const int tid = threadIdx.x;
    const int rb  = blockIdx.x * 8;
    for (int i = tid; i < 512; i += 256) {
        int r = i >> 6, k = i & 63;
        zt[r][k] = (k < 32) ? z1[(rb + r) * 32 + k] : z2[(rb + r) * 32 + (k - 32)];
    }
    __syncthreads();
    const int c4 = tid * 4;
    float acc[8][4];
    #pragma unroll
    for (int r = 0; r < 8; r++)
        #pragma unroll
        for (int c = 0; c < 4; c++) acc[r][c] = 0.f;
    for (int k = 0; k < 64; k++) {
        float4 w = *(const float4*)(W1 + k * 1024 + c4);
        #pragma unroll
        for (int r = 0; r < 8; r++) {
            float zv = zt[r][k];
            acc[r][0] += zv * w.x; acc[r][1] += zv * w.y;
            acc[r][2] += zv * w.z; acc[r][3] += zv * w.w;
        }
    }
    float4 bv = *(const float4*)(b1 + c4);
    #pragma unroll
    for (int r = 0; r < 8; r++) {
        float4 o;
        o.x = acc[r][0] + bv.x; o.y = acc[r][1] + bv.y;
        o.z = acc[r][2] + bv.z; o.w = acc[r][3] + bv.w;
        *(float4*)(g_xw1 + (size_t)(rb + r) * 1024 + c4) = o;
    }
}

// SMEM layout (floats):
//   h1s [256][HPAD], h2s [256][HPAD]  : per-unit, per-row hidden state
//   c1s [32][256],  c2s [32][256]     : cell state
//   prj [160][HPAD]                   : mu/lv exchange for sampling
#define SMEM_FLOATS (2 * 256 * HPAD + 2 * 32 * 256 + 160 * HPAD)
#define SMEM_BYTES  (SMEM_FLOATS * 4)

// grid 256, block 512. CTA b owns batch rows [32b, 32b+32).
// Thread t owns gate columns t (i or f) and t+512 (g or o) of unit (t & 255);
// rows are processed as 16 f32x2 pairs.
__global__ void __launch_bounds__(512, 1) lstm_kernel(
    const float* __restrict__ U1, const float* __restrict__ W2, const float* __restrict__ U2,
    const float* __restrict__ b2, const float* __restrict__ Wmu, const float* __restrict__ bmu,
    const float* __restrict__ Wlv, const float* __restrict__ blv,
    const float* __restrict__ eps, float* __restrict__ out)
{
    extern __shared__ float sm[];
    float* h1s = sm;
    float* h2s = sm + 256 * HPAD;
    float* c1s = sm + 2 * 256 * HPAD;
    float* c2s = c1s + 32 * 256;
    float* prj = c2s + 32 * 256;

    const int  tid  = threadIdx.x;
    const int  rb   = blockIdx.x * 32;
    const int  unit = tid & 255;
    const bool low  = tid < 256;
    const int  colA = tid;
    const int  colB = tid + 512;

    for (int i = tid; i < 2 * 256 * HPAD + 2 * 32 * 256; i += 512) sm[i] = 0.f;
    __syncthreads();

    const float b2A = b2[colA], b2B = b2[colB];

    // projection mapping: 480 threads = 160 cols (80 mu + 80 lv) x 3 row groups
    const bool  pact = tid < 480;
    const int   pcol = tid % 160;
    const int   prg  = tid / 160;
    const int   pr0  = prg * 12;            // rows 0..11, 12..23, 24..31
    const int   pnp  = (prg == 2) ? 4 : 6;  // row pairs in this group
    const float* pW  = (pcol < 80) ? Wmu : Wlv;
    const int   pf   = (pcol < 80) ? pcol : pcol - 80;
    const float pbias = pact ? ((pcol < 80) ? bmu[pf] : blv[pf]) : 0.f;

    ULL accA[16], accB[16];

    for (int t = 0; t < T_STEPS; t++) {
        // ---------- layer 1: z = xw1 + h1 @ U1 ----------
        {
            const float* xr = g_xw1 + (size_t)rb * 1024;
            #pragma unroll
            for (int p = 0; p < 16; p++) {
                accA[p] = pack2(xr[(2 * p) * 1024 + colA], xr[(2 * p + 1) * 1024 + colA]);
                accB[p] = pack2(xr[(2 * p) * 1024 + colB], xr[(2 * p + 1) * 1024 + colB]);
            }
        }
        #pragma unroll 2
        for (int k = 0; k < 256; k++) {
            float wa = U1[k * 1024 + colA];
            float wb = U1[k * 1024 + colB];
            ULL wa2 = pack2(wa, wa), wb2 = pack2(wb, wb);
            const ULL* hp = (const ULL*)(h1s + k * HPAD);
            #pragma unroll
            for (int p = 0; p < 16; p++) {
                ULL hv = hp[p];
                accA[p] = fma2(hv, wa2, accA[p]);
                accB[p] = fma2(hv, wb2, accB[p]);
            }
        }
        __syncthreads();
        if (low) {  // accA = i gate, accB = g gate: write sig(i)*tanh(g) into h1s
            #pragma unroll
            for (int p = 0; p < 16; p++) {
                float2 iv = unpack2(accA[p]);
                float2 gv = unpack2(accB[p]);
                h1s[unit * HPAD + 2 * p]     = sigf(iv.x) * tanhe(gv.x);
                h1s[unit * HPAD + 2 * p + 1] = sigf(iv.y) * tanhe(gv.y);
            }
        }
        __syncthreads();
        if (!low) { // accA = f gate, accB = o gate: finish c,h update
            #pragma unroll
            for (int p = 0; p < 16; p++) {
                float2 fv = unpack2(accA[p]);
                float2 ov = unpack2(accB[p]);
                int r = 2 * p;
                float ig0 = h1s[unit * HPAD + r], ig1 = h1s[unit * HPAD + r + 1];
                float c0  = c1s[r * 256 + unit],  c1v = c1s[(r + 1) * 256 + unit];
                float cn0 = sigf(fv.x) * c0  + ig0;
                float cn1 = sigf(fv.y) * c1v + ig1;
                c1s[r * 256 + unit]       = cn0;
                c1s[(r + 1) * 256 + unit] = cn1;
                h1s[unit * HPAD + r]     = sigf(ov.x) * tanhe(cn0);
                h1s[unit * HPAD + r + 1] = sigf(ov.y) * tanhe(cn1);
            }
        }
        __syncthreads();

        // ---------- layer 2: z = b2 + h1n @ W2 + h2 @ U2 ----------
        #pragma unroll
        for (int p = 0; p < 16; p++) { accA[p] = pack2(b2A, b2A); accB[p] = pack2(b2B, b2B); }
        #pragma unroll 2
        for (int k = 0; k < 256; k++) {
            float wa = W2[k * 1024 + colA];
            float wb = W2[k * 1024 + colB];
            float va = U2[k * 1024 + colA];
            float vb = U2[k * 1024 + colB];
            ULL wa2 = pack2(wa, wa), wb2 = pack2(wb, wb);
            ULL va2 = pack2(va, va), vb2 = pack2(vb, vb);
            const ULL* hp1 = (const ULL*)(h1s + k * HPAD);
            const ULL* hp2 = (const ULL*)(h2s + k * HPAD);
            #pragma unroll
            for (int p = 0; p < 16; p++) {
                ULL h1v = hp1[p], h2v = hp2[p];
                accA[p] = fma2(h1v, wa2, accA[p]);
                accB[p] = fma2(h1v, wb2, accB[p]);
                accA[p] = fma2(h2v, va2, accA[p]);
                accB[p] = fma2(h2v, vb2, accB[p]);
            }
        }
        __syncthreads();
        if (low) {
            #pragma unroll
            for (int p = 0; p < 16; p++) {
                float2 iv = unpack2(accA[p]);
                float2 gv = unpack2(accB[p]);
                h2s[unit * HPAD + 2 * p]     = sigf(iv.x) * tanhe(gv.x);
                h2s[unit * HPAD + 2 * p + 1] = sigf(iv.y) * tanhe(gv.y);
            }
        }
        __syncthreads();
        if (!low) {
            #pragma unroll
            for (int p = 0; p < 16; p++) {
                float2 fv = unpack2(accA[p]);
                float2 ov = unpack2(accB[p]);
                int r = 2 * p;
                float ig0 = h2s[unit * HPAD + r], ig1 = h2s[unit * HPAD + r + 1];
                float c0  = c2s[r * 256 + unit],  c1v = c2s[(r + 1) * 256 + unit];
                float cn0 = sigf(fv.x) * c0  + ig0;
                float cn1 = sigf(fv.y) * c1v + ig1;
                c2s[r * 256 + unit]       = cn0;
                c2s[(r + 1) * 256 + unit] = cn1;
                h2s[unit * HPAD + r]     = sigf(ov.x) * tanhe(cn0);
                h2s[unit * HPAD + r + 1] = sigf(ov.y) * tanhe(cn1);
            }
        }
        __syncthreads();

        // ---------- write output h2n: out[b][t][h] ----------
        #pragma unroll
        for (int j = 0; j < 16; j++) {
            int i = tid + j * 512;
            int r = i >> 8, h = i & 255;
            out[((size_t)(rb + r) * T_STEPS + t) * 256 + h] = h2s[h * HPAD + r];
        }

        // ---------- mu / logvar projection ----------
        if (pact) {
            ULL pacc[6];
            #pragma unroll
            for (int q = 0; q < 6; q++) pacc[q] = 0ULL;
            for (int k = 0; k < 256; k++) {
                float w = pW[k * 80 + pf];
                ULL w2 = pack2(w, w);
                const ULL* hp = (const ULL*)(h2s + k * HPAD + pr0);
                #pragma unroll
                for (int q = 0; q < 6; q++)
                    if (q < pnp) pacc[q] = fma2(hp[q], w2, pacc[q]);
            }
            #pragma unroll
            for (int q = 0; q < 6; q++) {
                if (q < pnp) {
                    float2 v = unpack2(pacc[q]);
                    prj[pcol * HPAD + pr0 + 2 * q]     = v.x + pbias;
                    prj[pcol * HPAD + pr0 + 2 * q + 1] = v.y + pbias;
                }
            }
        }
        __syncthreads();

        // ---------- sample = eps * exp(0.5*mu) + logvar; store mu/lv/sample ----------
        #pragma unroll
        for (int j = 0; j < 5; j++) {
            int i = tid + j * 512;
            int r = i / 80, f = i - r * 80;
            float mu = prj[f * HPAD + r];
            float lv = prj[(80 + f) * HPAD + r];
            size_t base = ((size_t)(rb + r) * T_STEPS + t) * 80 + f;
            float e = eps[base];
            out[41943040u + base] = mu;                           // x_mu
            out[55050240u + base] = lv;                           // x_logvar
            out[68157440u + base] = e * __expf(0.5f * mu) + lv;   // x_sample
        }
        // next write to prj/h buffers is behind multiple __syncthreads in t+1
    }
}

extern "C" void kernel_launch(void* const* d_in, const int* in_sizes, int n_in,
                              void* d_out, int out_size) {
    // metadata order: x, z1, z2, eps, W1, U1, b1, W2, U2, b2, Wmu, bmu, Wlv, blv
    const float* z1  = (const float*)d_in[1];
    const float* z2  = (const float*)d_in[2];
    const float* eps = (const float*)d_in[3];
    const float* W1  = (const float*)d_in[4];
    const float* U1  = (const float*)d_in[5];
    const float* b1  = (const float*)d_in[6];
    const float* W2  = (const float*)d_in[7];
    const float* U2  = (const float*)d_in[8];
    const float* b2  = (const float*)d_in[9];
    const float* Wmu = (const float*)d_in[10];
    const float* bmu = (const float*)d_in[11];
    const float* Wlv = (const float*)d_in[12];
    const float* blv = (const float*)d_in[13];
    float* out = (float*)d_out;

    cudaFuncSetAttribute(lstm_kernel, cudaFuncAttributeMaxDynamicSharedMemorySize, SMEM_BYTES);

    xw1_kernel<<<1024, 256>>>(z1, z2, W1, b1);
    lstm_kernel<<<256, 512, SMEM_BYTES>>>(U1, W2, U2, b2, Wmu, bmu, Wlv, blv, eps, out);
}

// round 2
// speedup vs baseline: 1.0954x; 1.0954x over previous
#include <cuda_runtime.h>

// ---------------------------------------------------------------------------
// 2-layer LSTM decoder. Persistent CTA = 32 batch rows. Thread = (unit, rowgrp):
// owns all 4 gates of one hidden unit for 16 rows. f32x2 FFMA throughout.
// Weights repacked into gate-quads (float4 per (k,unit)) for LDG.128.
// ---------------------------------------------------------------------------

#define ULL unsigned long long
#define T_STEPS 20
#define HP 36   // padded row stride (floats): 16B-aligned, 4-way-conflict STS only

__device__ __forceinline__ ULL pack2(float x, float y) {
    ULL r; asm("mov.b64 %0, {%1, %2};" : "=l"(r) : "f"(x), "f"(y)); return r;
}
__device__ __forceinline__ float2 unpack2(ULL v) {
    float2 r; asm("mov.b64 {%0, %1}, %2;" : "=f"(r.x), "=f"(r.y) : "l"(v)); return r;
}
__device__ __forceinline__ ULL fma2(ULL a, ULL b, ULL c) {
    ULL d; asm("fma.rn.f32x2 %0, %1, %2, %3;" : "=l"(d) : "l"(a), "l"(b), "l"(c)); return d;
}
__device__ __forceinline__ float sigf(float x)  { return __fdividef(1.f, 1.f + __expf(-x)); }
__device__ __forceinline__ float tanhe(float x) { return __fdividef(2.f, 1.f + __expf(-2.f * x)) - 1.f; }

// Static scratch (device globals are allowed; cudaMalloc is not).
__device__ float4 g_w1q [64  * 256];          // W1 gate quads  [k][u] = (i,f,g,o)
__device__ float4 g_u1q [256 * 256 + 256];    // U1 quads (+pad for prefetch)
__device__ float4 g_w2q [256 * 256 + 256];    // W2 quads
__device__ float4 g_u2q [256 * 256 + 256];    // U2 quads
__device__ float4 g_xw1q[8192 * 256];         // xw1 quads [row][u], bias folded in

// ---- repack weights into gate quads: quad[(k,u)] = {M[k][u], M[k][256+u], M[k][512+u], M[k][768+u]}
__global__ void repack_kernel(const float* __restrict__ W1, const float* __restrict__ U1,
                              const float* __restrict__ W2, const float* __restrict__ U2) {
    int i = blockIdx.x * blockDim.x + threadIdx.x;   // 0 .. 65535
    int k = i >> 8, u = i & 255;
    const float* r;
    if (i < 64 * 256) {
        r = W1 + k * 1024;
        g_w1q[i] = make_float4(r[u], r[256 + u], r[512 + u], r[768 + u]);
    }
    r = U1 + k * 1024; g_u1q[i] = make_float4(r[u], r[256 + u], r[512 + u], r[768 + u]);
    r = W2 + k * 1024; g_w2q[i] = make_float4(r[u], r[256 + u], r[512 + u], r[768 + u]);
    r = U2 + k * 1024; g_u2q[i] = make_float4(r[u], r[256 + u], r[512 + u], r[768 + u]);
}

// ---- xw1 = concat(z1,z2) @ W1 + b1, emitted as gate quads. grid 1024 x 256.
__global__ void xw1_kernel(const float* __restrict__ z1, const float* __restrict__ z2,
                           const float* __restrict__ b1) {
    __shared__ float zt[8][64];
    const int tid = threadIdx.x;
    const int rb  = blockIdx.x * 8;
    for (int i = tid; i < 512; i += 256) {
        int r = i >> 6, k = i & 63;
        zt[r][k] = (k < 32) ? z1[(rb + r) * 32 + k] : z2[(rb + r) * 32 + (k - 32)];
    }
    __syncthreads();
    const int u = tid;
    float4 acc[8];
    #pragma unroll
    for (int r = 0; r < 8; r++) acc[r] = make_float4(0.f, 0.f, 0.f, 0.f);
    for (int k = 0; k < 64; k++) {
        float4 w = g_w1q[k * 256 + u];
        #pragma unroll
        for (int r = 0; r < 8; r++) {
            float zv = zt[r][k];
            acc[r].x += zv * w.x; acc[r].y += zv * w.y;
            acc[r].z += zv * w.z; acc[r].w += zv * w.w;
        }
    }
    float4 bq = make_float4(b1[u], b1[256 + u], b1[512 + u], b1[768 + u]);
    #pragma unroll
    for (int r = 0; r < 8; r++) {
        float4 o = make_float4(acc[r].x + bq.x, acc[r].y + bq.y,
                               acc[r].z + bq.z, acc[r].w + bq.w);
        g_xw1q[(size_t)(rb + r) * 256 + u] = o;
    }
}

// SMEM: h1s/h2s/c1s/c2s [256][HP], prj [160][HP]
#define SMEM_FLOATS (4 * 256 * HP + 160 * HP)
#define SMEM_BYTES  (SMEM_FLOATS * 4)

__global__ void __launch_bounds__(512, 1) lstm_kernel(
    const float* __restrict__ b2,  const float* __restrict__ Wmu, const float* __restrict__ bmu,
    const float* __restrict__ Wlv, const float* __restrict__ blv,
    const float* __restrict__ eps, float* __restrict__ out)
{
    extern __shared__ float sm[];
    float* h1s = sm;
    float* h2s = sm + 256 * HP;
    float* c1s = sm + 2 * 256 * HP;
    float* c2s = sm + 3 * 256 * HP;
    float* prj = sm + 4 * 256 * HP;

    const int tid = threadIdx.x;
    const int u   = tid & 255;
    const int rg  = tid >> 8;      // 0/1
    const int r0  = rg * 16;       // local row base
    const int rb  = blockIdx.x * 32;

    for (int i = tid; i < 4 * 256 * HP; i += 512) sm[i] = 0.f;
    __syncthreads();

    const float4 b2q = make_float4(b2[u], b2[256 + u], b2[512 + u], b2[768 + u]);

    // projection mapping: 480 threads = 160 cols (80 mu + 80 lv) x 3 row groups
    const bool  pact = tid < 480;
    const int   pcol = tid % 160;
    const int   prg  = tid / 160;
    const int   pr0  = prg * 12;
    const int   pnp  = (prg == 2) ? 4 : 6;
    const float* pW  = (pcol < 80) ? Wmu : Wlv;
    const int   pf   = (pcol < 80) ? pcol : pcol - 80;
    const float pbias = pact ? ((pcol < 80) ? bmu[pf] : blv[pf]) : 0.f;

    const float4* xq  = g_xw1q + (size_t)(rb + r0) * 256 + u;
    const float4* u1p = g_u1q + u;
    const float4* w2p = g_w2q + u;
    const float4* u2p = g_u2q + u;

    ULL acc[4][8];

    for (int t = 0; t < T_STEPS; t++) {
        // ================= GEMV layer 1: acc = xw1 + h1_old @ U1 ==============
        #pragma unroll
        for (int p = 0; p < 8; p++) {
            float4 q0 = xq[(2 * p) * 256];
            float4 q1 = xq[(2 * p + 1) * 256];
            acc[0][p] = pack2(q0.x, q1.x);
            acc[1][p] = pack2(q0.y, q1.y);
            acc[2][p] = pack2(q0.z, q1.z);
            acc[3][p] = pack2(q0.w, q1.w);
        }
        {
            float4 w = u1p[0];
            const char* hb = (const char*)(h1s + r0);
            #pragma unroll 2
            for (int k = 0; k < 256; k++) {
                float4 wn = u1p[(k + 1) * 256];          // padded prefetch
                ULL wi = pack2(w.x, w.x), wf = pack2(w.y, w.y);
                ULL wg = pack2(w.z, w.z), wo = pack2(w.w, w.w);
                const ulonglong2* hp = (const ulonglong2*)(hb + (size_t)k * (HP * 4));
                ulonglong2 a0 = hp[0], a1 = hp[1], a2 = hp[2], a3 = hp[3];
                #pragma unroll
                for (int p = 0; p < 8; p++) {
                    ULL hv = (p == 0) ? a0.x : (p == 1) ? a0.y : (p == 2) ? a1.x : (p == 3) ? a1.y
                           : (p == 4) ? a2.x : (p == 5) ? a2.y : (p == 6) ? a3.x : a3.y;
                    acc[0][p] = fma2(hv, wi, acc[0][p]);
                    acc[1][p] = fma2(hv, wf, acc[1][p]);
                    acc[2][p] = fma2(hv, wg, acc[2][p]);
                    acc[3][p] = fma2(hv, wo, acc[3][p]);
                }
                w = wn;
            }
        }
        __syncthreads();
        // ---- gate 1: fully thread-local ----
        #pragma unroll
        for (int p = 0; p < 8; p++) {
            float2 iv = unpack2(acc[0][p]);
            float2 fv = unpack2(acc[1][p]);
            float2 gv = unpack2(acc[2][p]);
            float2 ov = unpack2(acc[3][p]);
            int rr = r0 + 2 * p;
            float c0 = c1s[u * HP + rr], c1 = c1s[u * HP + rr + 1];
            c0 = sigf(fv.x) * c0 + sigf(iv.x) * tanhe(gv.x);
            c1 = sigf(fv.y) * c1 + sigf(iv.y) * tanhe(gv.y);
            c1s[u * HP + rr]     = c0;
            c1s[u * HP + rr + 1] = c1;
            float2 hn = make_float2(sigf(ov.x) * tanhe(c0), sigf(ov.y) * tanhe(c1));
            *(float2*)(h1s + u * HP + rr) = hn;
        }
        __syncthreads();

        // ============ GEMV layer 2: acc = b2 + h1_new @ W2 + h2_old @ U2 ======
        #pragma unroll
        for (int p = 0; p < 8; p++) {
            acc[0][p] = pack2(b2q.x, b2q.x);
            acc[1][p] = pack2(b2q.y, b2q.y);
            acc[2][p] = pack2(b2q.z, b2q.z);
            acc[3][p] = pack2(b2q.w, b2q.w);
        }
        {
            float4 w = w2p[0], v = u2p[0];
            const char* hb1 = (const char*)(h1s + r0);
            const char* hb2 = (const char*)(h2s + r0);
            #pragma unroll 1
            for (int k = 0; k < 256; k++) {
                float4 wn = w2p[(k + 1) * 256];
                float4 vn = u2p[(k + 1) * 256];
                ULL wi = pack2(w.x, w.x), wf = pack2(w.y, w.y);
                ULL wg = pack2(w.z, w.z), wo = pack2(w.w, w.w);
                ULL vi = pack2(v.x, v.x), vf = pack2(v.y, v.y);
                ULL vg = pack2(v.z, v.z), vo = pack2(v.w, v.w);
                const ulonglong2* hp1 = (const ulonglong2*)(hb1 + (size_t)k * (HP * 4));
                const ulonglong2* hp2 = (const ulonglong2*)(hb2 + (size_t)k * (HP * 4));
                ulonglong2 a0 = hp1[0], a1 = hp1[1], a2 = hp1[2], a3 = hp1[3];
                ulonglong2 b0 = hp2[0], b1v = hp2[1], b2v = hp2[2], b3 = hp2[3];
                #pragma unroll
                for (int p = 0; p < 8; p++) {
                    ULL h1v = (p == 0) ? a0.x : (p == 1) ? a0.y : (p == 2) ? a1.x : (p == 3) ? a1.y
                            : (p == 4) ? a2.x : (p == 5) ? a2.y : (p == 6) ? a3.x : a3.y;
                    ULL h2v = (p == 0) ? b0.x : (p == 1) ? b0.y : (p == 2) ? b1v.x : (p == 3) ? b1v.y
                            : (p == 4) ? b2v.x : (p == 5) ? b2v.y : (p == 6) ? b3.x : b3.y;
                    acc[0][p] = fma2(h1v, wi, acc[0][p]);
                    acc[1][p] = fma2(h1v, wf, acc[1][p]);
                    acc[2][p] = fma2(h1v, wg, acc[2][p]);
                    acc[3][p] = fma2(h1v, wo, acc[3][p]);
                    acc[0][p] = fma2(h2v, vi, acc[0][p]);
                    acc[1][p] = fma2(h2v, vf, acc[1][p]);
                    acc[2][p] = fma2(h2v, vg, acc[2][p]);
                    acc[3][p] = fma2(h2v, vo, acc[3][p]);
                }
                w = wn; v = vn;
            }
        }
        __syncthreads();
        // ---- gate 2: local; h2 to smem (for GEMV/proj) AND straight to gmem ----
        #pragma unroll
        for (int p = 0; p < 8; p++) {
            float2 iv = unpack2(acc[0][p]);
            float2 fv = unpack2(acc[1][p]);
            float2 gv = unpack2(acc[2][p]);
            float2 ov = unpack2(acc[3][p]);
            int rr = r0 + 2 * p;
            float c0 = c2s[u * HP + rr], c1 = c2s[u * HP + rr + 1];
            c0 = sigf(fv.x) * c0 + sigf(iv.x) * tanhe(gv.x);
            c1 = sigf(fv.y) * c1 + sigf(iv.y) * tanhe(gv.y);
            c2s[u * HP + rr]     = c0;
            c2s[u * HP + rr + 1] = c1;
            float2 hn = make_float2(sigf(ov.x) * tanhe(c0), sigf(ov.y) * tanhe(c1));
            *(float2*)(h2s + u * HP + rr) = hn;
            out[((size_t)(rb + rr) * T_STEPS + t) * 256 + u]     = hn.x;
            out[((size_t)(rb + rr + 1) * T_STEPS + t) * 256 + u] = hn.y;
        }
        __syncthreads();

        // ---- mu / logvar projection ----
        if (pact) {
            ULL pacc[6];
            #pragma unroll
            for (int q = 0; q < 6; q++) pacc[q] = 0ULL;
            const char* hb = (const char*)(h2s + pr0);
            for (int k = 0; k < 256; k++) {
                float wv = pW[k * 80 + pf];
                ULL w2 = pack2(wv, wv);
                const ULL* hp = (const ULL*)(hb + (size_t)k * (HP * 4));
                #pragma unroll
                for (int q = 0; q < 6; q++)
                    if (q < pnp) pacc[q] = fma2(hp[q], w2, pacc[q]);
            }
            #pragma unroll
            for (int q = 0; q < 6; q++) {
                if (q < pnp) {
                    float2 v = unpack2(pacc[q]);
                    prj[pcol * HP + pr0 + 2 * q]     = v.x + pbias;
                    prj[pcol * HP + pr0 + 2 * q + 1] = v.y + pbias;
                }
            }
        }
        __syncthreads();

        // ---- sample = eps * exp(0.5*mu) + logvar ----
        #pragma unroll
        for (int j = 0; j < 5; j++) {
            int i = tid + j * 512;
            int r = i / 80, f = i - r * 80;
            float mu = prj[f * HP + r];
            float lv = prj[(80 + f) * HP + r];
            size_t base = ((size_t)(rb + r) * T_STEPS + t) * 80 + f;
            float e = eps[base];
            out[41943040u + base] = mu;
            out[55050240u + base] = lv;
            out[68157440u + base] = e * __expf(0.5f * mu) + lv;
        }
    }
}

extern "C" void kernel_launch(void* const* d_in, const int* in_sizes, int n_in,
                              void* d_out, int out_size) {
    // order: x, z1, z2, eps, W1, U1, b1, W2, U2, b2, Wmu, bmu, Wlv, blv
    const float* z1  = (const float*)d_in[1];
    const float* z2  = (const float*)d_in[2];
    const float* eps = (const float*)d_in[3];
    const float* W1  = (const float*)d_in[4];
    const float* U1  = (const float*)d_in[5];
    const float* b1  = (const float*)d_in[6];
    const float* W2  = (const float*)d_in[7];
    const float* U2  = (const float*)d_in[8];
    const float* b2  = (const float*)d_in[9];
    const float* Wmu = (const float*)d_in[10];
    const float* bmu = (const float*)d_in[11];
    const float* Wlv = (const float*)d_in[12];
    const float* blv = (const float*)d_in[13];
    float* out = (float*)d_out;

    cudaFuncSetAttribute(lstm_kernel, cudaFuncAttributeMaxDynamicSharedMemorySize, SMEM_BYTES);

    repack_kernel<<<256, 256>>>(W1, U1, W2, U2);
    xw1_kernel<<<1024, 256>>>(z1, z2, b1);
    lstm_kernel<<<256, 512, SMEM_BYTES>>>(b2, Wmu, bmu, Wlv, blv, eps, out);
}